// round 13
// baseline (speedup 1.0000x reference)
#include <cuda_runtime.h>
#include <cuda_fp16.h>
#include <cstdint>

// Problem constants (static per reference)
#define A_N    900      // anchors
#define P_N    13       // points
#define CAM_N  6        // cameras
#define LVL_N  4        // levels
#define CH     256      // channels
#define G_N    8        // groups (32 ch each)
#define SAMP   (P_N * CAM_N * LVL_N)   // 312 samples per anchor
#define THW    14960    // sum of H*W over levels
#define NWARP  16
#define FEAT_N (CAM_N * THW * CH)      // 22,978,560 elements

// Converter: persistent single-wave grid so the PDL trigger fires at t~0.
#define CVT_CTAS    148
#define CVT_THR     512
#define CVT_TOTAL   (CVT_CTAS * CVT_THR)

// Feature regions in 16-float units. Levels 1-3 = rows [11264,14960) per cam.
#define HI_ROW0            11264
#define HI_UNITS_PER_CAM   ((3696 * CH) / 16)    // 59136
#define HI_UNITS           (HI_UNITS_PER_CAM * CAM_N)
#define LO_UNITS_PER_CAM   ((11264 * CH) / 16)   // 180224
#define LO_UNITS           (LO_UNITS_PER_CAM * CAM_N)

// Gather processes 78 samples per level, level order {1,2,3,0}:
// slots [0,234) need levels 1-3 (flag A); slots [234,312) need level 0 (flag B).
#define HI_SLOTS  (3 * P_N * CAM_N)   // 234

__constant__ int c_H[LVL_N] = {64, 32, 16, 8};
__constant__ int c_W[LVL_N] = {176, 88, 44, 22};
__constant__ int c_S[LVL_N] = {0, 11264, 14080, 14784};

// fp16 copy of the feature tensor (45.9 MB) + sync flags (zero-init; the last
// gather CTA resets them so every graph replay starts clean).
__device__ __half    d_feath[FEAT_N];
__device__ unsigned  d_cntA;
__device__ unsigned  d_cntB;
__device__ unsigned  d_done;

// Convert 16 consecutive floats at float-index idx to fp16.
__device__ __forceinline__ void cvt16(const float* __restrict__ f, size_t idx)
{
    const float4 a = __ldcs(reinterpret_cast<const float4*>(f + idx));
    const float4 b = __ldcs(reinterpret_cast<const float4*>(f + idx + 4));
    const float4 c = __ldcs(reinterpret_cast<const float4*>(f + idx + 8));
    const float4 d = __ldcs(reinterpret_cast<const float4*>(f + idx + 12));
    __half2 h[8];
    h[0] = __floats2half2_rn(a.x, a.y);  h[1] = __floats2half2_rn(a.z, a.w);
    h[2] = __floats2half2_rn(b.x, b.y);  h[3] = __floats2half2_rn(b.z, b.w);
    h[4] = __floats2half2_rn(c.x, c.y);  h[5] = __floats2half2_rn(c.z, c.w);
    h[6] = __floats2half2_rn(d.x, d.y);  h[7] = __floats2half2_rn(d.z, d.w);
    uint4* dst = reinterpret_cast<uint4*>(d_feath + idx);
    dst[0] = reinterpret_cast<const uint4*>(h)[0];
    dst[1] = reinterpret_cast<const uint4*>(h)[1];
}

// ---------------- Kernel 1: persistent fp32 -> fp16 conversion ----------------
// 148 CTAs (one wave): launch_dependents fires immediately; levels 1-3
// converted first and released via d_cntA, then level 0 via d_cntB.
__global__ __launch_bounds__(CVT_THR)
void cvt_kernel(const float* __restrict__ f)
{
    asm volatile("griddepcontrol.launch_dependents;" ::: "memory");
    const unsigned t = blockIdx.x * CVT_THR + threadIdx.x;

    // Pass 1: levels 1-3 (rows [11264,14960) of each cam)
    for (unsigned u = t; u < HI_UNITS; u += CVT_TOTAL) {
        const unsigned cam = u / HI_UNITS_PER_CAM;
        const unsigned off = u - cam * HI_UNITS_PER_CAM;
        cvt16(f, ((size_t)cam * THW + HI_ROW0) * CH + (size_t)off * 16);
    }
    __threadfence();
    __syncthreads();
    if (threadIdx.x == 0) atomicAdd(&d_cntA, 1u);

    // Pass 2: level 0 (rows [0,11264) of each cam)
    for (unsigned u = t; u < LO_UNITS; u += CVT_TOTAL) {
        const unsigned cam = u / LO_UNITS_PER_CAM;
        const unsigned off = u - cam * LO_UNITS_PER_CAM;
        cvt16(f, (size_t)cam * THW * CH + (size_t)off * 16);
    }
    __threadfence();
    __syncthreads();
    if (threadIdx.x == 0) atomicAdd(&d_cntB, 1u);
}

// One sample: bilinear combine in HFMA2 (pre-packed half2 corner weights),
// then fp32 FMA applies the group weight into the fp32 accumulator (R11 math).
__device__ __forceinline__ void sample_acc(
    const uint4& u0, const uint4& u1, const uint4& u2, const uint4& u3,
    const uint4& cwp, const float wg, float2* acc)
{
    const __half2* c  = reinterpret_cast<const __half2*>(&cwp);
    const __half2* h0 = reinterpret_cast<const __half2*>(&u0);
    const __half2* h1 = reinterpret_cast<const __half2*>(&u1);
    const __half2* h2 = reinterpret_cast<const __half2*>(&u2);
    const __half2* h3 = reinterpret_cast<const __half2*>(&u3);
    #pragma unroll
    for (int j = 0; j < 4; j++) {
        __half2 v = __hmul2(c[0], h0[j]);
        v = __hfma2(c[1], h1[j], v);
        v = __hfma2(c[2], h2[j], v);
        v = __hfma2(c[3], h3[j], v);
        const float2 fv = __half22float2(v);
        acc[j].x = fmaf(wg, fv.x, acc[j].x);
        acc[j].y = fmaf(wg, fv.y, acc[j].y);
    }
}

// Process slots [lo,hi) with the proven 2-sample interleave (8 LDG.128 in flight).
__device__ __forceinline__ void gather_range(
    int lo, int hi, int warp, int lane, int g,
    const int4* s_idx, const uint4* s_cwh, const float (*s_w)[G_N],
    float2* acc)
{
    int i = lo + warp;
    for (; i + NWARP < hi; i += 2 * NWARP) {
        const int j = i + NWARP;
        const int4 ia = s_idx[i];
        const int4 ib = s_idx[j];
        const uint4 pa0 = *(reinterpret_cast<const uint4*>(d_feath + (size_t)ia.x * CH) + lane);
        const uint4 pa1 = *(reinterpret_cast<const uint4*>(d_feath + (size_t)ia.y * CH) + lane);
        const uint4 pa2 = *(reinterpret_cast<const uint4*>(d_feath + (size_t)ia.z * CH) + lane);
        const uint4 pa3 = *(reinterpret_cast<const uint4*>(d_feath + (size_t)ia.w * CH) + lane);
        const uint4 pb0 = *(reinterpret_cast<const uint4*>(d_feath + (size_t)ib.x * CH) + lane);
        const uint4 pb1 = *(reinterpret_cast<const uint4*>(d_feath + (size_t)ib.y * CH) + lane);
        const uint4 pb2 = *(reinterpret_cast<const uint4*>(d_feath + (size_t)ib.z * CH) + lane);
        const uint4 pb3 = *(reinterpret_cast<const uint4*>(d_feath + (size_t)ib.w * CH) + lane);
        sample_acc(pa0, pa1, pa2, pa3, s_cwh[i], s_w[i][g], acc);
        sample_acc(pb0, pb1, pb2, pb3, s_cwh[j], s_w[j][g], acc);
    }
    if (i < hi) {
        const int4 ia = s_idx[i];
        const uint4 pa0 = *(reinterpret_cast<const uint4*>(d_feath + (size_t)ia.x * CH) + lane);
        const uint4 pa1 = *(reinterpret_cast<const uint4*>(d_feath + (size_t)ia.y * CH) + lane);
        const uint4 pa2 = *(reinterpret_cast<const uint4*>(d_feath + (size_t)ia.z * CH) + lane);
        const uint4 pa3 = *(reinterpret_cast<const uint4*>(d_feath + (size_t)ia.w * CH) + lane);
        sample_acc(pa0, pa1, pa2, pa3, s_cwh[i], s_w[i][g], acc);
    }
}

// Block-wide wait until *flag reaches target (set by cvt passes).
__device__ __forceinline__ void wait_flag(const unsigned* flag, unsigned target)
{
    if (threadIdx.x == 0) {
        const volatile unsigned* p = flag;
        while (*p < target) {}
        __threadfence();
    }
    __syncthreads();
}

// ---------------- Kernel 2: gather ----------------
// One CTA per anchor, 512 threads = 16 warps (R8-proven shape). Samples are
// ordered level-major {1,2,3,0}: the lvl1-3 phase overlaps cvt's level-0 pass.
__global__ __launch_bounds__(512, 2)
void daf_gather(const float* __restrict__ points,    // [1,900,13,6,2]
                const float* __restrict__ weights,   // [1,900,13,6,4,8]
                float* __restrict__ out)             // [1,900,256]
{
    const int a   = blockIdx.x;
    const int tid = threadIdx.x;

    __shared__ int4  s_idx[SAMP];        // 4 corner row indices
    __shared__ uint4 s_cwh[SAMP];        // 4 bilinear*valid weights as half2
    __shared__ float s_w  [SAMP][G_N];   // 8 group weights (fp32)
    __shared__ float s_red[NWARP][CH];   // per-warp partials

    // ---------- Phase 1: per-sample metadata (independent of cvt) ----------
    if (tid < SAMP) {
        const int s      = tid;                 // permuted slot
        const int lvlOrd = s / (P_N * CAM_N);   // 0..3
        const int within = s - lvlOrd * (P_N * CAM_N);
        const int pt     = within / CAM_N;
        const int cam    = within - pt * CAM_N;
        const int lvl    = (lvlOrd + 1) & 3;    // order 1,2,3,0

        const float2 p = *reinterpret_cast<const float2*>(
            points + (((size_t)a * P_N + pt) * CAM_N + cam) * 2);

        const int h = c_H[lvl], w = c_W[lvl];
        const float x = p.x * (float)w - 0.5f;
        const float y = p.y * (float)h - 0.5f;
        const float x0f = floorf(x), y0f = floorf(y);
        const int   x0  = (int)x0f,  y0  = (int)y0f;
        const float fx  = x - x0f,   fy  = y - y0f;
        const float wx[2] = {1.0f - fx, fx};
        const float wy[2] = {1.0f - fy, fy};
        const int base = cam * THW + c_S[lvl];

        int     vi[4];
        __half2 vc[4];
        #pragma unroll
        for (int k = 0; k < 4; k++) {
            const int dx = k & 1, dy = k >> 1;
            const int xi = x0 + dx, yi = y0 + dy;
            const bool valid = (xi >= 0) & (xi < w) & (yi >= 0) & (yi < h);
            const int xc = min(max(xi, 0), w - 1);
            const int yc = min(max(yi, 0), h - 1);
            vi[k] = base + yc * w + xc;
            vc[k] = __float2half2_rn(valid ? wx[dx] * wy[dy] : 0.0f);
        }
        s_idx[s] = make_int4(vi[0], vi[1], vi[2], vi[3]);
        s_cwh[s] = *reinterpret_cast<const uint4*>(vc);

        const float4* wp = reinterpret_cast<const float4*>(
            weights + ((((size_t)a * P_N + pt) * CAM_N + cam) * LVL_N + lvl) * G_N);
        float4* wd = reinterpret_cast<float4*>(&s_w[s][0]);
        wd[0] = wp[0];
        wd[1] = wp[1];
    }
    __syncthreads();

    const int warp = tid >> 5;
    const int lane = tid & 31;
    const int g    = lane >> 2;   // group of this lane's 8 channels

    float2 acc[4] = {{0.f,0.f},{0.f,0.f},{0.f,0.f},{0.f,0.f}};

    // ---------- Phase 2a: levels 1-3 (overlaps cvt's level-0 pass) ----------
    wait_flag(&d_cntA, CVT_CTAS);
    gather_range(0, HI_SLOTS, warp, lane, g, s_idx, s_cwh, s_w, acc);

    // ---------- Phase 2b: level 0 ----------
    wait_flag(&d_cntB, CVT_CTAS);
    gather_range(HI_SLOTS, SAMP, warp, lane, g, s_idx, s_cwh, s_w, acc);

    // ---------- Phase 3: reduce 16 warps, write output directly ----------
    {
        float4* dst = reinterpret_cast<float4*>(&s_red[warp][lane * 8]);
        dst[0] = make_float4(acc[0].x, acc[0].y, acc[1].x, acc[1].y);
        dst[1] = make_float4(acc[2].x, acc[2].y, acc[3].x, acc[3].y);
    }
    __syncthreads();

    if (tid < 64) {
        float4 r = make_float4(0.f, 0.f, 0.f, 0.f);
        #pragma unroll
        for (int w = 0; w < NWARP; w++) {
            const float4 t = reinterpret_cast<const float4*>(&s_red[w][0])[tid];
            r.x += t.x; r.y += t.y; r.z += t.z; r.w += t.w;
        }
        reinterpret_cast<float4*>(out + (size_t)a * CH)[tid] = r;
    }

    // ---------- Phase 4: last CTA resets flags for the next replay ----------
    if (tid == 0) {
        __threadfence();
        const unsigned t = atomicAdd(&d_done, 1u);
        if (t == A_N - 1) {
            d_cntA = 0;
            d_cntB = 0;
            d_done = 0;
        }
    }
}

extern "C" void kernel_launch(void* const* d_in, const int* in_sizes, int n_in,
                              void* d_out, int out_size)
{
    const float* feature = (const float*)d_in[0];
    // d_in[1] = spatial_shapes, d_in[2] = level_start_index (static, hardcoded)
    const float* points  = (const float*)d_in[3];
    const float* weights = (const float*)d_in[4];
    float* out = (float*)d_out;

    cvt_kernel<<<CVT_CTAS, CVT_THR>>>(feature);

    // PDL: cvt is a single wave, so launch_dependents fires at t~0 and the
    // gather truly overlaps the conversion; data readiness is flag-gated.
    cudaLaunchConfig_t cfg = {};
    cfg.gridDim  = dim3(A_N);
    cfg.blockDim = dim3(512);
    cfg.stream   = 0;
    cudaLaunchAttribute attr[1];
    attr[0].id = cudaLaunchAttributeProgrammaticStreamSerialization;
    attr[0].val.programmaticStreamSerializationAllowed = 1;
    cfg.attrs = attr;
    cfg.numAttrs = 1;
    cudaLaunchKernelEx(&cfg, daf_gather, points, weights, out);
}